// round 13
// baseline (speedup 1.0000x reference)
#include <cuda_runtime.h>
#include <cuda_bf16.h>

// GATv2 x2 — CSR node-centric, parallel scan, fused l/r GEMM pairs, deep MLP
#define NMAX 50000
#define EMAX 800000

// -------- scratch (device globals; no allocations allowed) ----------
__device__ __align__(16) float g_xl1[NMAX * 64];
__device__ __align__(16) float g_xr1[NMAX * 64];
__device__ __align__(16) float g_agg1[NMAX * 64];   // holds h = relu(agg+b1)
__device__ __align__(16) float g_xl2[NMAX * 32];
__device__ __align__(16) float g_xr2[NMAX * 32];

// CSR by destination node (built once, reused by both layers)
__device__ int g_deg[NMAX];
__device__ int g_off[NMAX + 1];
__device__ int g_pos[NMAX];
__device__ int g_csrc[EMAX];
__device__ int g_bsum[256];

// -------- CSR build -------------------------------------------------
__global__ void zerodeg_kernel(int n) {
    int i = blockIdx.x * blockDim.x + threadIdx.x;
    if (i < n) g_deg[i] = 0;
}

// 2 edges per thread, int2 index loads
__global__ void count_kernel(const int* __restrict__ ei, int nE) {
    int i = blockIdx.x * blockDim.x + threadIdx.x;
    int e = i * 2;
    if (e + 1 < nE) {
        int2 d2 = *(const int2*)(ei + nE + e);
        atomicAdd(&g_deg[d2.x], 1);
        atomicAdd(&g_deg[d2.y], 1);
    } else if (e < nE) {
        atomicAdd(&g_deg[ei[nE + e]], 1);
    }
}

// phase A: per-block sums of g_deg chunks (grid = 256 blocks, 256 thr)
__global__ void scanA_kernel(int n) {
    __shared__ int sm[256];
    int b = blockIdx.x, t = threadIdx.x;
    int chunk = (n + 255) / 256;
    int i = b * chunk + t;
    int v = (t < chunk && i < n) ? g_deg[i] : 0;
    sm[t] = v;
    __syncthreads();
#pragma unroll
    for (int o = 128; o > 0; o >>= 1) {
        if (t < o) sm[t] += sm[t + o];
        __syncthreads();
    }
    if (t == 0) g_bsum[b] = sm[0];
}

// phase B: 1 block shuffle-scans the 256 block sums (exclusive)
__global__ void scanB_kernel(int n, int nE) {
    __shared__ int wsum[8];
    int t = threadIdx.x;
    int lane = t & 31;
    int wid = t >> 5;
    int v = g_bsum[t];
    int incl = v;
#pragma unroll
    for (int o = 1; o < 32; o <<= 1) {
        int u = __shfl_up_sync(0xffffffffu, incl, o);
        if (lane >= o) incl += u;
    }
    if (lane == 31) wsum[wid] = incl;
    __syncthreads();
    if (wid == 0 && lane < 8) {
        int w = wsum[lane];
        int wincl = w;
#pragma unroll
        for (int o = 1; o < 8; o <<= 1) {
            int u = __shfl_up_sync(0xffu, wincl, o);
            if (lane >= o) wincl += u;
        }
        wsum[lane] = wincl - w;   // exclusive warp base
    }
    __syncthreads();
    g_bsum[t] = wsum[wid] + incl - v;   // exclusive prefix
    if (t == 0) g_off[n] = nE;
}

// phase C: local exclusive scan + base, write g_off / g_pos
__global__ void scanC_kernel(int n) {
    __shared__ int sm[256];
    int b = blockIdx.x, t = threadIdx.x;
    int chunk = (n + 255) / 256;
    int i = b * chunk + t;
    int v = (t < chunk && i < n) ? g_deg[i] : 0;
    sm[t] = v;
    __syncthreads();
#pragma unroll
    for (int o = 1; o < 256; o <<= 1) {
        int u = (t >= o) ? sm[t - o] : 0;
        __syncthreads();
        sm[t] += u;
        __syncthreads();
    }
    int off = g_bsum[b] + sm[t] - v;   // exclusive
    if (t < chunk && i < n) {
        g_off[i] = off;
        g_pos[i] = off;
    }
}

// 2 edges per thread, int2 index loads
__global__ void fill_kernel(const int* __restrict__ ei, int nE) {
    int i = blockIdx.x * blockDim.x + threadIdx.x;
    int e = i * 2;
    if (e + 1 < nE) {
        int2 s2 = *(const int2*)(ei + e);
        int2 d2 = *(const int2*)(ei + nE + e);
        int p0 = atomicAdd(&g_pos[d2.x], 1);
        int p1 = atomicAdd(&g_pos[d2.y], 1);
        g_csrc[p0] = s2.x;
        g_csrc[p1] = s2.y;
    } else if (e < nE) {
        int s = ei[e];
        int d = ei[nE + e];
        int p = atomicAdd(&g_pos[d], 1);
        g_csrc[p] = s;
    }
}

// -------- fused GEMM pair, layer 1: x[128] -> xl1[64], xr1[64] ------
__global__ void __launch_bounds__(256)
gemm_pair1(const float* __restrict__ X, const float* __restrict__ Wla,
           const float* __restrict__ Wra, int n)
{
    __shared__ __align__(16) float Wl[64 * 64];
    __shared__ __align__(16) float Wr[64 * 64];

    int tid = threadIdx.x;
    int tx = tid & 15;
    int ty = tid >> 4;
    int rbase = blockIdx.x * 64 + ty;

    float accl[4][4], accr[4][4];
#pragma unroll
    for (int r = 0; r < 4; r++)
#pragma unroll
        for (int c = 0; c < 4; c++) { accl[r][c] = 0.f; accr[r][c] = 0.f; }

    int rows[4];
#pragma unroll
    for (int r = 0; r < 4; r++) {
        int row = rbase + 16 * r;
        rows[r] = row < n ? row : (n - 1);
    }

    for (int kc = 0; kc < 128; kc += 64) {
        const float4* sl = (const float4*)(Wla + kc * 64);
        const float4* sr = (const float4*)(Wra + kc * 64);
        for (int i = tid; i < 1024; i += 256) {
            ((float4*)Wl)[i] = sl[i];
            ((float4*)Wr)[i] = sr[i];
        }
        __syncthreads();

        for (int k = 0; k < 64; k += 4) {
            float xv[4][4];
#pragma unroll
            for (int r = 0; r < 4; r++) {
                float4 x4 = *(const float4*)(X + (size_t)rows[r] * 128 + kc + k);
                xv[r][0] = x4.x; xv[r][1] = x4.y; xv[r][2] = x4.z; xv[r][3] = x4.w;
            }
#pragma unroll
            for (int kk = 0; kk < 4; kk++) {
                float4 wl4 = *(const float4*)(Wl + (k + kk) * 64 + tx * 4);
                float4 wr4 = *(const float4*)(Wr + (k + kk) * 64 + tx * 4);
#pragma unroll
                for (int r = 0; r < 4; r++) {
                    float xs = xv[r][kk];
                    accl[r][0] = fmaf(xs, wl4.x, accl[r][0]);
                    accl[r][1] = fmaf(xs, wl4.y, accl[r][1]);
                    accl[r][2] = fmaf(xs, wl4.z, accl[r][2]);
                    accl[r][3] = fmaf(xs, wl4.w, accl[r][3]);
                    accr[r][0] = fmaf(xs, wr4.x, accr[r][0]);
                    accr[r][1] = fmaf(xs, wr4.y, accr[r][1]);
                    accr[r][2] = fmaf(xs, wr4.z, accr[r][2]);
                    accr[r][3] = fmaf(xs, wr4.w, accr[r][3]);
                }
            }
        }
        __syncthreads();
    }

#pragma unroll
    for (int r = 0; r < 4; r++) {
        int row = rbase + 16 * r;
        if (row < n) {
            *(float4*)(g_xl1 + (size_t)row * 64 + tx * 4) =
                make_float4(accl[r][0], accl[r][1], accl[r][2], accl[r][3]);
            *(float4*)(g_xr1 + (size_t)row * 64 + tx * 4) =
                make_float4(accr[r][0], accr[r][1], accr[r][2], accr[r][3]);
        }
    }
}

// -------- fused GEMM pair, layer 2: h[64] -> xl2[32], xr2[32] -------
__global__ void __launch_bounds__(256)
gemm_pair2(const float* __restrict__ Wla, const float* __restrict__ Wra, int n)
{
    __shared__ __align__(16) float Wl[64 * 32];
    __shared__ __align__(16) float Wr[64 * 32];
    const float* __restrict__ X = (const float*)g_agg1;

    int tid = threadIdx.x;
    int tx = tid & 15;
    int ty = tid >> 4;
    int rbase = blockIdx.x * 64 + ty;

    for (int i = tid; i < 512; i += 256) {
        ((float4*)Wl)[i] = ((const float4*)Wla)[i];
        ((float4*)Wr)[i] = ((const float4*)Wra)[i];
    }
    __syncthreads();

    float accl[4][2], accr[4][2];
#pragma unroll
    for (int r = 0; r < 4; r++)
#pragma unroll
        for (int c = 0; c < 2; c++) { accl[r][c] = 0.f; accr[r][c] = 0.f; }

    int rows[4];
#pragma unroll
    for (int r = 0; r < 4; r++) {
        int row = rbase + 16 * r;
        rows[r] = row < n ? row : (n - 1);
    }

    for (int k = 0; k < 64; k += 4) {
        float xv[4][4];
#pragma unroll
        for (int r = 0; r < 4; r++) {
            float4 x4 = *(const float4*)(X + (size_t)rows[r] * 64 + k);
            xv[r][0] = x4.x; xv[r][1] = x4.y; xv[r][2] = x4.z; xv[r][3] = x4.w;
        }
#pragma unroll
        for (int kk = 0; kk < 4; kk++) {
            float2 wl2 = *(const float2*)(Wl + (k + kk) * 32 + tx * 2);
            float2 wr2 = *(const float2*)(Wr + (k + kk) * 32 + tx * 2);
#pragma unroll
            for (int r = 0; r < 4; r++) {
                float xs = xv[r][kk];
                accl[r][0] = fmaf(xs, wl2.x, accl[r][0]);
                accl[r][1] = fmaf(xs, wl2.y, accl[r][1]);
                accr[r][0] = fmaf(xs, wr2.x, accr[r][0]);
                accr[r][1] = fmaf(xs, wr2.y, accr[r][1]);
            }
        }
    }

#pragma unroll
    for (int r = 0; r < 4; r++) {
        int row = rbase + 16 * r;
        if (row < n) {
            *(float2*)(g_xl2 + (size_t)row * 32 + tx * 2) =
                make_float2(accl[r][0], accl[r][1]);
            *(float2*)(g_xr2 + (size_t)row * 32 + tx * 2) =
                make_float2(accr[r][0], accr[r][1]);
        }
    }
}

__device__ __forceinline__ float leaky02(float v) {
    return fmaxf(v, 0.2f * v);
}

// -------- layer 1 node kernel: warp/node, half-warp/edge, float4 ----
// main loop: 8 edges per iteration (4 per half-warp) for deep MLP
__global__ void node_layer1(const float* __restrict__ att,
                            const float* __restrict__ b1, int n)
{
    int lane = threadIdx.x & 31;
    int warp = (blockIdx.x * blockDim.x + threadIdx.x) >> 5;
    int nw = (gridDim.x * blockDim.x) >> 5;
    int half = lane >> 4;
    int c = lane & 15;
    float4 av = ((const float4*)att)[c];
    float4 bv = ((const float4*)b1)[c];

    for (int node = warp; node < n; node += nw) {
        int beg = g_off[node];
        int end = g_off[node + 1];
        float4 xr = ((const float4*)(g_xr1 + node * 64))[c];
        float4 acc = make_float4(0.f, 0.f, 0.f, 0.f);
        float den = 0.f;

        int i = beg;
        for (; i + 7 < end; i += 8) {
            int sA = g_csrc[i + half];
            int sB = g_csrc[i + 2 + half];
            int sC = g_csrc[i + 4 + half];
            int sD = g_csrc[i + 6 + half];
            float4 aA = ((const float4*)(g_xl1 + sA * 64))[c];
            float4 aB = ((const float4*)(g_xl1 + sB * 64))[c];
            float4 aC = ((const float4*)(g_xl1 + sC * 64))[c];
            float4 aD = ((const float4*)(g_xl1 + sD * 64))[c];
            float vA = leaky02(aA.x + xr.x) * av.x + leaky02(aA.y + xr.y) * av.y
                     + leaky02(aA.z + xr.z) * av.z + leaky02(aA.w + xr.w) * av.w;
            float vB = leaky02(aB.x + xr.x) * av.x + leaky02(aB.y + xr.y) * av.y
                     + leaky02(aB.z + xr.z) * av.z + leaky02(aB.w + xr.w) * av.w;
            float vC = leaky02(aC.x + xr.x) * av.x + leaky02(aC.y + xr.y) * av.y
                     + leaky02(aC.z + xr.z) * av.z + leaky02(aC.w + xr.w) * av.w;
            float vD = leaky02(aD.x + xr.x) * av.x + leaky02(aD.y + xr.y) * av.y
                     + leaky02(aD.z + xr.z) * av.z + leaky02(aD.w + xr.w) * av.w;
#pragma unroll
            for (int o = 8; o > 0; o >>= 1) {
                vA += __shfl_xor_sync(0xffffffffu, vA, o);
                vB += __shfl_xor_sync(0xffffffffu, vB, o);
                vC += __shfl_xor_sync(0xffffffffu, vC, o);
                vD += __shfl_xor_sync(0xffffffffu, vD, o);
            }
            float wA = __expf(vA);
            float wB = __expf(vB);
            float wC = __expf(vC);
            float wD = __expf(vD);
            acc.x += (wA * aA.x + wB * aB.x) + (wC * aC.x + wD * aD.x);
            acc.y += (wA * aA.y + wB * aB.y) + (wC * aC.y + wD * aD.y);
            acc.z += (wA * aA.z + wB * aB.z) + (wC * aC.z + wD * aD.z);
            acc.w += (wA * aA.w + wB * aB.w) + (wC * aC.w + wD * aD.w);
            den += (wA + wB) + (wC + wD);
        }
        for (; i + 3 < end; i += 4) {
            int sA = g_csrc[i + half];
            int sB = g_csrc[i + 2 + half];
            float4 aA = ((const float4*)(g_xl1 + sA * 64))[c];
            float4 aB = ((const float4*)(g_xl1 + sB * 64))[c];
            float vA = leaky02(aA.x + xr.x) * av.x + leaky02(aA.y + xr.y) * av.y
                     + leaky02(aA.z + xr.z) * av.z + leaky02(aA.w + xr.w) * av.w;
            float vB = leaky02(aB.x + xr.x) * av.x + leaky02(aB.y + xr.y) * av.y
                     + leaky02(aB.z + xr.z) * av.z + leaky02(aB.w + xr.w) * av.w;
#pragma unroll
            for (int o = 8; o > 0; o >>= 1) {
                vA += __shfl_xor_sync(0xffffffffu, vA, o);
                vB += __shfl_xor_sync(0xffffffffu, vB, o);
            }
            float wA = __expf(vA);
            float wB = __expf(vB);
            acc.x += wA * aA.x + wB * aB.x;
            acc.y += wA * aA.y + wB * aB.y;
            acc.z += wA * aA.z + wB * aB.z;
            acc.w += wA * aA.w + wB * aB.w;
            den += wA + wB;
        }
        for (; i < end; i += 2) {
            int e = i + half;
            bool valid = e < end;
            int s = g_csrc[valid ? e : (end - 1)];
            float4 a = ((const float4*)(g_xl1 + s * 64))[c];
            float v = leaky02(a.x + xr.x) * av.x + leaky02(a.y + xr.y) * av.y
                    + leaky02(a.z + xr.z) * av.z + leaky02(a.w + xr.w) * av.w;
#pragma unroll
            for (int o = 8; o > 0; o >>= 1)
                v += __shfl_xor_sync(0xffffffffu, v, o);
            float w = valid ? __expf(v) : 0.f;
            acc.x += w * a.x; acc.y += w * a.y;
            acc.z += w * a.z; acc.w += w * a.w;
            den += w;
        }

        acc.x += __shfl_xor_sync(0xffffffffu, acc.x, 16);
        acc.y += __shfl_xor_sync(0xffffffffu, acc.y, 16);
        acc.z += __shfl_xor_sync(0xffffffffu, acc.z, 16);
        acc.w += __shfl_xor_sync(0xffffffffu, acc.w, 16);
        den   += __shfl_xor_sync(0xffffffffu, den, 16);

        if (half == 0) {
            float inv = 1.f / (den + 1e-16f);
            float4 h;
            h.x = fmaxf(acc.x * inv + bv.x, 0.f);
            h.y = fmaxf(acc.y * inv + bv.y, 0.f);
            h.z = fmaxf(acc.z * inv + bv.z, 0.f);
            h.w = fmaxf(acc.w * inv + bv.w, 0.f);
            ((float4*)(g_agg1 + node * 64))[c] = h;
        }
    }
}

// -------- layer 2 node kernel: warp/node, quarter-warp/edge ---------
// main loop: 16 edges per iteration (4 per quarter-warp)
__global__ void node_layer2(const float* __restrict__ att,
                            const float* __restrict__ b2,
                            float* __restrict__ out, int n)
{
    int lane = threadIdx.x & 31;
    int warp = (blockIdx.x * blockDim.x + threadIdx.x) >> 5;
    int nw = (gridDim.x * blockDim.x) >> 5;
    int q = lane >> 3;
    int c = lane & 7;
    float4 av = ((const float4*)att)[c];
    float4 bv = ((const float4*)b2)[c];

    for (int node = warp; node < n; node += nw) {
        int beg = g_off[node];
        int end = g_off[node + 1];
        float4 xr = ((const float4*)(g_xr2 + node * 32))[c];
        float4 acc = make_float4(0.f, 0.f, 0.f, 0.f);
        float den = 0.f;

        int i = beg;
        for (; i + 15 < end; i += 16) {
            int sA = g_csrc[i + q];
            int sB = g_csrc[i + 4 + q];
            int sC = g_csrc[i + 8 + q];
            int sD = g_csrc[i + 12 + q];
            float4 aA = ((const float4*)(g_xl2 + sA * 32))[c];
            float4 aB = ((const float4*)(g_xl2 + sB * 32))[c];
            float4 aC = ((const float4*)(g_xl2 + sC * 32))[c];
            float4 aD = ((const float4*)(g_xl2 + sD * 32))[c];
            float vA = leaky02(aA.x + xr.x) * av.x + leaky02(aA.y + xr.y) * av.y
                     + leaky02(aA.z + xr.z) * av.z + leaky02(aA.w + xr.w) * av.w;
            float vB = leaky02(aB.x + xr.x) * av.x + leaky02(aB.y + xr.y) * av.y
                     + leaky02(aB.z + xr.z) * av.z + leaky02(aB.w + xr.w) * av.w;
            float vC = leaky02(aC.x + xr.x) * av.x + leaky02(aC.y + xr.y) * av.y
                     + leaky02(aC.z + xr.z) * av.z + leaky02(aC.w + xr.w) * av.w;
            float vD = leaky02(aD.x + xr.x) * av.x + leaky02(aD.y + xr.y) * av.y
                     + leaky02(aD.z + xr.z) * av.z + leaky02(aD.w + xr.w) * av.w;
#pragma unroll
            for (int o = 4; o > 0; o >>= 1) {
                vA += __shfl_xor_sync(0xffffffffu, vA, o);
                vB += __shfl_xor_sync(0xffffffffu, vB, o);
                vC += __shfl_xor_sync(0xffffffffu, vC, o);
                vD += __shfl_xor_sync(0xffffffffu, vD, o);
            }
            float wA = __expf(vA);
            float wB = __expf(vB);
            float wC = __expf(vC);
            float wD = __expf(vD);
            acc.x += (wA * aA.x + wB * aB.x) + (wC * aC.x + wD * aD.x);
            acc.y += (wA * aA.y + wB * aB.y) + (wC * aC.y + wD * aD.y);
            acc.z += (wA * aA.z + wB * aB.z) + (wC * aC.z + wD * aD.z);
            acc.w += (wA * aA.w + wB * aB.w) + (wC * aC.w + wD * aD.w);
            den += (wA + wB) + (wC + wD);
        }
        for (; i + 7 < end; i += 8) {
            int sA = g_csrc[i + q];
            int sB = g_csrc[i + 4 + q];
            float4 aA = ((const float4*)(g_xl2 + sA * 32))[c];
            float4 aB = ((const float4*)(g_xl2 + sB * 32))[c];
            float vA = leaky02(aA.x + xr.x) * av.x + leaky02(aA.y + xr.y) * av.y
                     + leaky02(aA.z + xr.z) * av.z + leaky02(aA.w + xr.w) * av.w;
            float vB = leaky02(aB.x + xr.x) * av.x + leaky02(aB.y + xr.y) * av.y
                     + leaky02(aB.z + xr.z) * av.z + leaky02(aB.w + xr.w) * av.w;
#pragma unroll
            for (int o = 4; o > 0; o >>= 1) {
                vA += __shfl_xor_sync(0xffffffffu, vA, o);
                vB += __shfl_xor_sync(0xffffffffu, vB, o);
            }
            float wA = __expf(vA);
            float wB = __expf(vB);
            acc.x += wA * aA.x + wB * aB.x;
            acc.y += wA * aA.y + wB * aB.y;
            acc.z += wA * aA.z + wB * aB.z;
            acc.w += wA * aA.w + wB * aB.w;
            den += wA + wB;
        }
        for (; i < end; i += 4) {
            int e = i + q;
            bool valid = e < end;
            int s = g_csrc[valid ? e : (end - 1)];
            float4 a = ((const float4*)(g_xl2 + s * 32))[c];
            float v = leaky02(a.x + xr.x) * av.x + leaky02(a.y + xr.y) * av.y
                    + leaky02(a.z + xr.z) * av.z + leaky02(a.w + xr.w) * av.w;
#pragma unroll
            for (int o = 4; o > 0; o >>= 1)
                v += __shfl_xor_sync(0xffffffffu, v, o);
            float w = valid ? __expf(v) : 0.f;
            acc.x += w * a.x; acc.y += w * a.y;
            acc.z += w * a.z; acc.w += w * a.w;
            den += w;
        }

#pragma unroll
        for (int o = 8; o <= 16; o <<= 1) {
            acc.x += __shfl_xor_sync(0xffffffffu, acc.x, o);
            acc.y += __shfl_xor_sync(0xffffffffu, acc.y, o);
            acc.z += __shfl_xor_sync(0xffffffffu, acc.z, o);
            acc.w += __shfl_xor_sync(0xffffffffu, acc.w, o);
            den   += __shfl_xor_sync(0xffffffffu, den, o);
        }

        if (q == 0) {
            float inv = 1.f / (den + 1e-16f);
            float4 v4;
            v4.x = acc.x * inv + bv.x;
            v4.y = acc.y * inv + bv.y;
            v4.z = acc.z * inv + bv.z;
            v4.w = acc.w * inv + bv.w;
            float4 o4;
            o4.x = fmaxf(v4.x, 0.f) + log1pf(__expf(-fabsf(v4.x))) + 1e-6f;
            o4.y = fmaxf(v4.y, 0.f) + log1pf(__expf(-fabsf(v4.y))) + 1e-6f;
            o4.z = fmaxf(v4.z, 0.f) + log1pf(__expf(-fabsf(v4.z))) + 1e-6f;
            o4.w = fmaxf(v4.w, 0.f) + log1pf(__expf(-fabsf(v4.w))) + 1e-6f;
            ((float4*)(out + node * 32))[c] = o4;
        }
    }
}

// ====================================================================
extern "C" void kernel_launch(void* const* d_in, const int* in_sizes, int n_in,
                              void* d_out, int out_size)
{
    const float* x    = (const float*)d_in[0];
    const int*   ei   = (const int*)d_in[1];    // int32 per harness dtype contract
    const float* W1l  = (const float*)d_in[2];
    const float* W1r  = (const float*)d_in[3];
    const float* att1 = (const float*)d_in[4];
    const float* b1   = (const float*)d_in[5];
    const float* W2l  = (const float*)d_in[6];
    const float* W2r  = (const float*)d_in[7];
    const float* att2 = (const float*)d_in[8];
    const float* b2   = (const float*)d_in[9];
    float*       out  = (float*)d_out;

    int n = in_sizes[0] / 128;   // 50000
    int E = in_sizes[1] / 2;     // 800000

    int gemm_blocks = (n + 63) / 64;
    int node_blocks = (n * 32 + 255) / 256;  // warp per node
    int edge2_blocks = (E / 2 + 255) / 256;  // 2 edges per thread

    // CSR build (dst-indexed), reused by both layers
    zerodeg_kernel<<<(n + 255) / 256, 256>>>(n);
    count_kernel<<<edge2_blocks, 256>>>(ei, E);
    scanA_kernel<<<256, 256>>>(n);
    scanB_kernel<<<1, 256>>>(n, E);
    scanC_kernel<<<256, 256>>>(n);
    fill_kernel<<<edge2_blocks, 256>>>(ei, E);

    // layer 1
    gemm_pair1<<<gemm_blocks, 256>>>(x, W1l, W1r, n);
    node_layer1<<<node_blocks, 256>>>(att1, b1, n);   // stores h = relu(.+b1)

    // layer 2 (g_agg1 holds h)
    gemm_pair2<<<gemm_blocks, 256>>>(W2l, W2r, n);
    node_layer2<<<node_blocks, 256>>>(att2, b2, out, n);  // fused softplus -> d_out
}

// round 14
// speedup vs baseline: 1.1036x; 1.1036x over previous
#include <cuda_runtime.h>
#include <cuda_bf16.h>

// GATv2 x2 — CSR node-centric, fused grid-sync scan, stream-overlapped GEMM
#define NMAX 50000
#define EMAX 800000

// -------- scratch (device globals; no allocations allowed) ----------
__device__ __align__(16) float g_xl1[NMAX * 64];
__device__ __align__(16) float g_xr1[NMAX * 64];
__device__ __align__(16) float g_agg1[NMAX * 64];   // holds h = relu(agg+b1)
__device__ __align__(16) float g_xl2[NMAX * 32];
__device__ __align__(16) float g_xr2[NMAX * 32];

// CSR by destination node (built once, reused by both layers)
// g_deg is zero at module load and re-zeroed by scan_fused each call.
__device__ int g_deg[NMAX];
__device__ int g_off[NMAX + 1];
__device__ int g_pos[NMAX];
__device__ int g_csrc[EMAX];
__device__ int g_bsum[256];
__device__ unsigned g_cnt;     // grid-barrier arrivals (zero-init, self-reset)
__device__ unsigned g_sense;   // grid-barrier generation

// -------- CSR build -------------------------------------------------
// 2 edges per thread, int2 index loads
__global__ void count_kernel(const int* __restrict__ ei, int nE) {
    int i = blockIdx.x * blockDim.x + threadIdx.x;
    int e = i * 2;
    if (e + 1 < nE) {
        int2 d2 = *(const int2*)(ei + nE + e);
        atomicAdd(&g_deg[d2.x], 1);
        atomicAdd(&g_deg[d2.y], 1);
    } else if (e < nE) {
        atomicAdd(&g_deg[ei[nE + e]], 1);
    }
}

// fused 3-phase exclusive scan: 256 blocks, one internal grid barrier.
// Also self-cleans g_deg to zero for the next call.
__global__ void __launch_bounds__(256) scan_fused(int n, int nE) {
    __shared__ int sm[256];
    int b = blockIdx.x, t = threadIdx.x;
    int chunk = (n + 255) / 256;
    int i = b * chunk + t;
    bool live = (t < chunk && i < n);
    int v = live ? g_deg[i] : 0;

    // block-local inclusive scan
    sm[t] = v;
    __syncthreads();
#pragma unroll
    for (int o = 1; o < 256; o <<= 1) {
        int u = (t >= o) ? sm[t - o] : 0;
        __syncthreads();
        sm[t] += u;
        __syncthreads();
    }
    int incl = sm[t];
    if (t == 255) g_bsum[b] = incl;   // block total

    // grid barrier (sense-reversing; 256 blocks are all co-resident)
    __threadfence();
    __syncthreads();
    if (t == 0) {
        unsigned gen = atomicAdd(&g_sense, 0u);
        unsigned my = atomicAdd(&g_cnt, 1u);
        if (my == 255u) {
            atomicExch(&g_cnt, 0u);
            __threadfence();
            atomicAdd(&g_sense, 1u);
        } else {
            while (atomicAdd(&g_sense, 0u) == gen) {}
        }
    }
    __syncthreads();

    // every block reduces its own base = sum of bsum[0..b-1]
    sm[t] = (t < b) ? g_bsum[t] : 0;
    __syncthreads();
#pragma unroll
    for (int o = 128; o > 0; o >>= 1) {
        if (t < o) sm[t] += sm[t + o];
        __syncthreads();
    }
    int base = sm[0];

    int off = base + incl - v;   // exclusive prefix
    if (live) {
        g_off[i] = off;
        g_pos[i] = off;
        g_deg[i] = 0;            // self-clean for next call
    }
    if (b == 255 && t == 0) g_off[n] = nE;
}

// 2 edges per thread, int2 index loads
__global__ void fill_kernel(const int* __restrict__ ei, int nE) {
    int i = blockIdx.x * blockDim.x + threadIdx.x;
    int e = i * 2;
    if (e + 1 < nE) {
        int2 s2 = *(const int2*)(ei + e);
        int2 d2 = *(const int2*)(ei + nE + e);
        int p0 = atomicAdd(&g_pos[d2.x], 1);
        int p1 = atomicAdd(&g_pos[d2.y], 1);
        g_csrc[p0] = s2.x;
        g_csrc[p1] = s2.y;
    } else if (e < nE) {
        int s = ei[e];
        int d = ei[nE + e];
        int p = atomicAdd(&g_pos[d], 1);
        g_csrc[p] = s;
    }
}

// -------- fused GEMM pair, layer 1: x[128] -> xl1[64], xr1[64] ------
__global__ void __launch_bounds__(256)
gemm_pair1(const float* __restrict__ X, const float* __restrict__ Wla,
           const float* __restrict__ Wra, int n)
{
    __shared__ __align__(16) float Wl[64 * 64];
    __shared__ __align__(16) float Wr[64 * 64];

    int tid = threadIdx.x;
    int tx = tid & 15;
    int ty = tid >> 4;
    int rbase = blockIdx.x * 64 + ty;

    float accl[4][4], accr[4][4];
#pragma unroll
    for (int r = 0; r < 4; r++)
#pragma unroll
        for (int c = 0; c < 4; c++) { accl[r][c] = 0.f; accr[r][c] = 0.f; }

    int rows[4];
#pragma unroll
    for (int r = 0; r < 4; r++) {
        int row = rbase + 16 * r;
        rows[r] = row < n ? row : (n - 1);
    }

    for (int kc = 0; kc < 128; kc += 64) {
        const float4* sl = (const float4*)(Wla + kc * 64);
        const float4* sr = (const float4*)(Wra + kc * 64);
        for (int i = tid; i < 1024; i += 256) {
            ((float4*)Wl)[i] = sl[i];
            ((float4*)Wr)[i] = sr[i];
        }
        __syncthreads();

        for (int k = 0; k < 64; k += 4) {
            float xv[4][4];
#pragma unroll
            for (int r = 0; r < 4; r++) {
                float4 x4 = *(const float4*)(X + (size_t)rows[r] * 128 + kc + k);
                xv[r][0] = x4.x; xv[r][1] = x4.y; xv[r][2] = x4.z; xv[r][3] = x4.w;
            }
#pragma unroll
            for (int kk = 0; kk < 4; kk++) {
                float4 wl4 = *(const float4*)(Wl + (k + kk) * 64 + tx * 4);
                float4 wr4 = *(const float4*)(Wr + (k + kk) * 64 + tx * 4);
#pragma unroll
                for (int r = 0; r < 4; r++) {
                    float xs = xv[r][kk];
                    accl[r][0] = fmaf(xs, wl4.x, accl[r][0]);
                    accl[r][1] = fmaf(xs, wl4.y, accl[r][1]);
                    accl[r][2] = fmaf(xs, wl4.z, accl[r][2]);
                    accl[r][3] = fmaf(xs, wl4.w, accl[r][3]);
                    accr[r][0] = fmaf(xs, wr4.x, accr[r][0]);
                    accr[r][1] = fmaf(xs, wr4.y, accr[r][1]);
                    accr[r][2] = fmaf(xs, wr4.z, accr[r][2]);
                    accr[r][3] = fmaf(xs, wr4.w, accr[r][3]);
                }
            }
        }
        __syncthreads();
    }

#pragma unroll
    for (int r = 0; r < 4; r++) {
        int row = rbase + 16 * r;
        if (row < n) {
            *(float4*)(g_xl1 + (size_t)row * 64 + tx * 4) =
                make_float4(accl[r][0], accl[r][1], accl[r][2], accl[r][3]);
            *(float4*)(g_xr1 + (size_t)row * 64 + tx * 4) =
                make_float4(accr[r][0], accr[r][1], accr[r][2], accr[r][3]);
        }
    }
}

// -------- fused GEMM pair, layer 2: h[64] -> xl2[32], xr2[32] -------
__global__ void __launch_bounds__(256)
gemm_pair2(const float* __restrict__ Wla, const float* __restrict__ Wra, int n)
{
    __shared__ __align__(16) float Wl[64 * 32];
    __shared__ __align__(16) float Wr[64 * 32];
    const float* __restrict__ X = (const float*)g_agg1;

    int tid = threadIdx.x;
    int tx = tid & 15;
    int ty = tid >> 4;
    int rbase = blockIdx.x * 64 + ty;

    for (int i = tid; i < 512; i += 256) {
        ((float4*)Wl)[i] = ((const float4*)Wla)[i];
        ((float4*)Wr)[i] = ((const float4*)Wra)[i];
    }
    __syncthreads();

    float accl[4][2], accr[4][2];
#pragma unroll
    for (int r = 0; r < 4; r++)
#pragma unroll
        for (int c = 0; c < 2; c++) { accl[r][c] = 0.f; accr[r][c] = 0.f; }

    int rows[4];
#pragma unroll
    for (int r = 0; r < 4; r++) {
        int row = rbase + 16 * r;
        rows[r] = row < n ? row : (n - 1);
    }

    for (int k = 0; k < 64; k += 4) {
        float xv[4][4];
#pragma unroll
        for (int r = 0; r < 4; r++) {
            float4 x4 = *(const float4*)(X + (size_t)rows[r] * 64 + k);
            xv[r][0] = x4.x; xv[r][1] = x4.y; xv[r][2] = x4.z; xv[r][3] = x4.w;
        }
#pragma unroll
        for (int kk = 0; kk < 4; kk++) {
            float2 wl2 = *(const float2*)(Wl + (k + kk) * 32 + tx * 2);
            float2 wr2 = *(const float2*)(Wr + (k + kk) * 32 + tx * 2);
#pragma unroll
            for (int r = 0; r < 4; r++) {
                float xs = xv[r][kk];
                accl[r][0] = fmaf(xs, wl2.x, accl[r][0]);
                accl[r][1] = fmaf(xs, wl2.y, accl[r][1]);
                accr[r][0] = fmaf(xs, wr2.x, accr[r][0]);
                accr[r][1] = fmaf(xs, wr2.y, accr[r][1]);
            }
        }
    }

#pragma unroll
    for (int r = 0; r < 4; r++) {
        int row = rbase + 16 * r;
        if (row < n) {
            *(float2*)(g_xl2 + (size_t)row * 32 + tx * 2) =
                make_float2(accl[r][0], accl[r][1]);
            *(float2*)(g_xr2 + (size_t)row * 32 + tx * 2) =
                make_float2(accr[r][0], accr[r][1]);
        }
    }
}

__device__ __forceinline__ float leaky02(float v) {
    return fmaxf(v, 0.2f * v);
}

// -------- layer 1 node kernel: warp/node, half-warp/edge, float4 ----
__global__ void node_layer1(const float* __restrict__ att,
                            const float* __restrict__ b1, int n)
{
    int lane = threadIdx.x & 31;
    int warp = (blockIdx.x * blockDim.x + threadIdx.x) >> 5;
    int nw = (gridDim.x * blockDim.x) >> 5;
    int half = lane >> 4;
    int c = lane & 15;
    float4 av = ((const float4*)att)[c];
    float4 bv = ((const float4*)b1)[c];

    for (int node = warp; node < n; node += nw) {
        int beg = g_off[node];
        int end = g_off[node + 1];
        float4 xr = ((const float4*)(g_xr1 + node * 64))[c];
        float4 acc = make_float4(0.f, 0.f, 0.f, 0.f);
        float den = 0.f;

        int i = beg;
        for (; i + 3 < end; i += 4) {
            int sA = g_csrc[i + half];
            int sB = g_csrc[i + 2 + half];
            float4 aA = ((const float4*)(g_xl1 + sA * 64))[c];
            float4 aB = ((const float4*)(g_xl1 + sB * 64))[c];
            float vA = leaky02(aA.x + xr.x) * av.x + leaky02(aA.y + xr.y) * av.y
                     + leaky02(aA.z + xr.z) * av.z + leaky02(aA.w + xr.w) * av.w;
            float vB = leaky02(aB.x + xr.x) * av.x + leaky02(aB.y + xr.y) * av.y
                     + leaky02(aB.z + xr.z) * av.z + leaky02(aB.w + xr.w) * av.w;
#pragma unroll
            for (int o = 8; o > 0; o >>= 1) {
                vA += __shfl_xor_sync(0xffffffffu, vA, o);
                vB += __shfl_xor_sync(0xffffffffu, vB, o);
            }
            float wA = __expf(vA);
            float wB = __expf(vB);
            acc.x += wA * aA.x + wB * aB.x;
            acc.y += wA * aA.y + wB * aB.y;
            acc.z += wA * aA.z + wB * aB.z;
            acc.w += wA * aA.w + wB * aB.w;
            den += wA + wB;
        }
        for (; i < end; i += 2) {
            int e = i + half;
            bool valid = e < end;
            int s = g_csrc[valid ? e : (end - 1)];
            float4 a = ((const float4*)(g_xl1 + s * 64))[c];
            float v = leaky02(a.x + xr.x) * av.x + leaky02(a.y + xr.y) * av.y
                    + leaky02(a.z + xr.z) * av.z + leaky02(a.w + xr.w) * av.w;
#pragma unroll
            for (int o = 8; o > 0; o >>= 1)
                v += __shfl_xor_sync(0xffffffffu, v, o);
            float w = valid ? __expf(v) : 0.f;
            acc.x += w * a.x; acc.y += w * a.y;
            acc.z += w * a.z; acc.w += w * a.w;
            den += w;
        }

        acc.x += __shfl_xor_sync(0xffffffffu, acc.x, 16);
        acc.y += __shfl_xor_sync(0xffffffffu, acc.y, 16);
        acc.z += __shfl_xor_sync(0xffffffffu, acc.z, 16);
        acc.w += __shfl_xor_sync(0xffffffffu, acc.w, 16);
        den   += __shfl_xor_sync(0xffffffffu, den, 16);

        if (half == 0) {
            float inv = 1.f / (den + 1e-16f);
            float4 h;
            h.x = fmaxf(acc.x * inv + bv.x, 0.f);
            h.y = fmaxf(acc.y * inv + bv.y, 0.f);
            h.z = fmaxf(acc.z * inv + bv.z, 0.f);
            h.w = fmaxf(acc.w * inv + bv.w, 0.f);
            ((float4*)(g_agg1 + node * 64))[c] = h;
        }
    }
}

// -------- layer 2 node kernel: warp/node, quarter-warp/edge ---------
__global__ void node_layer2(const float* __restrict__ att,
                            const float* __restrict__ b2,
                            float* __restrict__ out, int n)
{
    int lane = threadIdx.x & 31;
    int warp = (blockIdx.x * blockDim.x + threadIdx.x) >> 5;
    int nw = (gridDim.x * blockDim.x) >> 5;
    int q = lane >> 3;
    int c = lane & 7;
    float4 av = ((const float4*)att)[c];
    float4 bv = ((const float4*)b2)[c];

    for (int node = warp; node < n; node += nw) {
        int beg = g_off[node];
        int end = g_off[node + 1];
        float4 xr = ((const float4*)(g_xr2 + node * 32))[c];
        float4 acc = make_float4(0.f, 0.f, 0.f, 0.f);
        float den = 0.f;

        int i = beg;
        for (; i + 7 < end; i += 8) {
            int sA = g_csrc[i + q];
            int sB = g_csrc[i + 4 + q];
            float4 aA = ((const float4*)(g_xl2 + sA * 32))[c];
            float4 aB = ((const float4*)(g_xl2 + sB * 32))[c];
            float vA = leaky02(aA.x + xr.x) * av.x + leaky02(aA.y + xr.y) * av.y
                     + leaky02(aA.z + xr.z) * av.z + leaky02(aA.w + xr.w) * av.w;
            float vB = leaky02(aB.x + xr.x) * av.x + leaky02(aB.y + xr.y) * av.y
                     + leaky02(aB.z + xr.z) * av.z + leaky02(aB.w + xr.w) * av.w;
#pragma unroll
            for (int o = 4; o > 0; o >>= 1) {
                vA += __shfl_xor_sync(0xffffffffu, vA, o);
                vB += __shfl_xor_sync(0xffffffffu, vB, o);
            }
            float wA = __expf(vA);
            float wB = __expf(vB);
            acc.x += wA * aA.x + wB * aB.x;
            acc.y += wA * aA.y + wB * aB.y;
            acc.z += wA * aA.z + wB * aB.z;
            acc.w += wA * aA.w + wB * aB.w;
            den += wA + wB;
        }
        for (; i < end; i += 4) {
            int e = i + q;
            bool valid = e < end;
            int s = g_csrc[valid ? e : (end - 1)];
            float4 a = ((const float4*)(g_xl2 + s * 32))[c];
            float v = leaky02(a.x + xr.x) * av.x + leaky02(a.y + xr.y) * av.y
                    + leaky02(a.z + xr.z) * av.z + leaky02(a.w + xr.w) * av.w;
#pragma unroll
            for (int o = 4; o > 0; o >>= 1)
                v += __shfl_xor_sync(0xffffffffu, v, o);
            float w = valid ? __expf(v) : 0.f;
            acc.x += w * a.x; acc.y += w * a.y;
            acc.z += w * a.z; acc.w += w * a.w;
            den += w;
        }

#pragma unroll
        for (int o = 8; o <= 16; o <<= 1) {
            acc.x += __shfl_xor_sync(0xffffffffu, acc.x, o);
            acc.y += __shfl_xor_sync(0xffffffffu, acc.y, o);
            acc.z += __shfl_xor_sync(0xffffffffu, acc.z, o);
            acc.w += __shfl_xor_sync(0xffffffffu, acc.w, o);
            den   += __shfl_xor_sync(0xffffffffu, den, o);
        }

        if (q == 0) {
            float inv = 1.f / (den + 1e-16f);
            float4 v4;
            v4.x = acc.x * inv + bv.x;
            v4.y = acc.y * inv + bv.y;
            v4.z = acc.z * inv + bv.z;
            v4.w = acc.w * inv + bv.w;
            float4 o4;
            o4.x = fmaxf(v4.x, 0.f) + log1pf(__expf(-fabsf(v4.x))) + 1e-6f;
            o4.y = fmaxf(v4.y, 0.f) + log1pf(__expf(-fabsf(v4.y))) + 1e-6f;
            o4.z = fmaxf(v4.z, 0.f) + log1pf(__expf(-fabsf(v4.z))) + 1e-6f;
            o4.w = fmaxf(v4.w, 0.f) + log1pf(__expf(-fabsf(v4.w))) + 1e-6f;
            ((float4*)(out + node * 32))[c] = o4;
        }
    }
}

// ====================================================================
extern "C" void kernel_launch(void* const* d_in, const int* in_sizes, int n_in,
                              void* d_out, int out_size)
{
    const float* x    = (const float*)d_in[0];
    const int*   ei   = (const int*)d_in[1];    // int32 per harness dtype contract
    const float* W1l  = (const float*)d_in[2];
    const float* W1r  = (const float*)d_in[3];
    const float* att1 = (const float*)d_in[4];
    const float* b1   = (const float*)d_in[5];
    const float* W2l  = (const float*)d_in[6];
    const float* W2r  = (const float*)d_in[7];
    const float* att2 = (const float*)d_in[8];
    const float* b2   = (const float*)d_in[9];
    float*       out  = (float*)d_out;

    int n = in_sizes[0] / 128;   // 50000
    int E = in_sizes[1] / 2;     // 800000

    int gemm_blocks = (n + 63) / 64;
    int node_blocks = (n * 32 + 255) / 256;  // warp per node
    int edge2_blocks = (E / 2 + 255) / 256;  // 2 edges per thread

    // Side stream + events for overlapping gemm_pair1 with the CSR build.
    // Created per call; never destroyed (host-side only, kernel_launch runs
    // a handful of times — timed replays go through the captured graph).
    cudaStream_t s2;
    cudaStreamCreateWithFlags(&s2, cudaStreamNonBlocking);
    cudaEvent_t e1, e2;
    cudaEventCreateWithFlags(&e1, cudaEventDisableTiming);
    cudaEventCreateWithFlags(&e2, cudaEventDisableTiming);

    // fork: gemm_pair1 on s2 (depends only on inputs)
    cudaEventRecord(e1, 0);
    cudaStreamWaitEvent(s2, e1, 0);
    gemm_pair1<<<gemm_blocks, 256, 0, s2>>>(x, W1l, W1r, n);
    cudaEventRecord(e2, s2);

    // CSR build on the main stream (g_deg starts zero; scan_fused re-zeroes)
    count_kernel<<<edge2_blocks, 256>>>(ei, E);
    scan_fused<<<256, 256>>>(n, E);
    fill_kernel<<<edge2_blocks, 256>>>(ei, E);

    // join: node_layer1 needs CSR + xl1/xr1
    cudaStreamWaitEvent(0, e2, 0);
    node_layer1<<<node_blocks, 256>>>(att1, b1, n);   // stores h = relu(.+b1)

    // layer 2 (g_agg1 holds h)
    gemm_pair2<<<gemm_blocks, 256>>>(W2l, W2r, n);
    node_layer2<<<node_blocks, 256>>>(att2, b2, out, n);  // fused softplus -> d_out
}